// round 17
// baseline (speedup 1.0000x reference)
#include <cuda_runtime.h>
#include <cuda_fp16.h>
#include <math.h>
#include <stdint.h>

#define NB 64
#define TT 512
#define DD 1024
#define HH 1024
#define FOURH 4096
#define P_CTAS 128

// ---------------------------------------------------------------------------
// Scratch (__device__ globals; allocation-free rule)
// ---------------------------------------------------------------------------
__device__ __half   g_xw[(size_t)NB * TT * FOURH];      // 256 MiB xW+b fp16 (permuted cols)
__device__ __half   g_xh[(size_t)NB * TT * DD];         // 64 MiB x fp16
__device__ __half   g_wxt[(size_t)FOURH * DD];          // WxT perm [j'][k] fp16
__device__ __half   g_wht[(size_t)FOURH * DD];          // WhT perm [j'][k] fp16
__device__ __half   g_h[2][NB * HH];                    // h double buffer (fp16)
__device__ float    g_biasp[FOURH];                     // permuted bias
__device__ unsigned g_flags[P_CTAS * 32];               // per-CTA step flags (128B apart)

// ---------------------------------------------------------------------------
// Helpers
// ---------------------------------------------------------------------------
__device__ __forceinline__ uint32_t smem_u32(const void* p) {
    uint32_t a;
    asm("{ .reg .u64 t; cvta.to.shared.u64 t, %1; cvt.u32.u64 %0, t; }"
        : "=r"(a) : "l"(p));
    return a;
}
__device__ __forceinline__ unsigned ld_acq(const unsigned* p) {
    unsigned v;
    asm volatile("ld.global.acquire.gpu.u32 %0, [%1];" : "=r"(v) : "l"(p) : "memory");
    return v;
}
__device__ __forceinline__ void st_rel(unsigned* p, unsigned v) {
    asm volatile("st.global.release.gpu.u32 [%0], %1;" :: "l"(p), "r"(v) : "memory");
}

#define CP16(dst, src) \
    asm volatile("cp.async.cg.shared.global [%0], [%1], 16;" :: "r"(dst), "l"(src) : "memory")
#define CP_COMMIT() asm volatile("cp.async.commit_group;" ::: "memory")
#define CP_WAIT(n)  asm volatile("cp.async.wait_group %0;" :: "n"(n) : "memory")

#define LDSM4(r0, r1, r2, r3, addr) \
    asm volatile("ldmatrix.sync.aligned.m8n8.x4.shared.b16 {%0,%1,%2,%3}, [%4];" \
                 : "=r"(r0), "=r"(r1), "=r"(r2), "=r"(r3) : "r"(addr))

#define MMA_F16(c0, c1, c2, c3, a0, a1, a2, a3, b0, b1) \
    asm volatile("mma.sync.aligned.m16n8k16.row.col.f32.f16.f16.f32 " \
                 "{%0,%1,%2,%3}, {%4,%5,%6,%7}, {%8,%9}, {%0,%1,%2,%3};" \
                 : "+f"(c0), "+f"(c1), "+f"(c2), "+f"(c3) \
                 : "r"(a0), "r"(a1), "r"(a2), "r"(a3), "r"(b0), "r"(b1))

__device__ __forceinline__ float fsigmoid(float x) { return 1.0f / (1.0f + __expf(-x)); }
__device__ __forceinline__ float ftanh(float x)    { return 2.0f / (1.0f + __expf(-2.0f * x)) - 1.0f; }

// ---------------------------------------------------------------------------
// Prep kernels
// ---------------------------------------------------------------------------
__global__ void prep_small_kernel(const float* __restrict__ h0, const float* __restrict__ b) {
    int i = blockIdx.x * 1024 + threadIdx.x;
    if (i < P_CTAS * 32) g_flags[i] = 0u;
    if (i < NB * HH) {
        g_h[0][i] = __float2half_rn(h0[i]);
    }
    if (i < FOURH) {
        int jp = (i & 1023) * 4 + (i >> 10);     // perm: col g*1024+jh -> jh*4+g
        g_biasp[jp] = b[i];
    }
}

__global__ void split_x_kernel(const float* __restrict__ x) {
    size_t i = ((size_t)blockIdx.x * 256 + threadIdx.x) * 4;
    float4 v = *(const float4*)(x + i);
    __half2* ph = (__half2*)(g_xh + i);
    ph[0] = __floats2half2_rn(v.x, v.y);
    ph[1] = __floats2half2_rn(v.z, v.w);
}

// W (1024 x 4096, k-major rows) -> out[j'][k] fp16 with gate permutation.
__global__ void transpose_perm_kernel(const float* __restrict__ W,
                                      __half* __restrict__ o) {
    __shared__ float ts[32][33];
    const int k0 = blockIdx.x * 32;
    const int c0 = blockIdx.y * 32;
    const int tx = threadIdx.x, ty = threadIdx.y;  // 32 x 8
    #pragma unroll
    for (int i = 0; i < 4; i++)
        ts[ty + 8 * i][tx] = W[(size_t)(k0 + ty + 8 * i) * FOURH + c0 + tx];
    __syncthreads();
    #pragma unroll
    for (int i = 0; i < 4; i++) {
        int c = c0 + ty + 8 * i;
        int jp = (c & 1023) * 4 + (c >> 10);
        o[(size_t)jp * DD + k0 + tx] = __float2half_rn(ts[tx][ty + 8 * i]);
    }
}

// ---------------------------------------------------------------------------
// xW GEMM via mma.sync, single fp16 term: g_xw[token][j'] = fp16(x @ WxT^T + b)
// CTA tile 128(token) x 128(j'), k-chunk 64, 3-stage cp.async pipeline.
// ---------------------------------------------------------------------------
#define G_STAGE 32768   // A 16K | B 16K
#define G_SMEM  (3 * G_STAGE)

__global__ __launch_bounds__(256, 1)
void xw_gemm_mma() {
    extern __shared__ char smem[];
    const uint32_t sb = smem_u32(smem);
    const int tid = threadIdx.x;
    const int nbase = blockIdx.x * 128;
    const int mbase = blockIdx.y * 128;

    const __half* Ag = g_xh + (size_t)mbase * DD;
    const __half* Bg = g_wxt + (size_t)nbase * DD;

    auto cp_chunk = [&](int c, int st) {
        const int k0 = c * 64;
        const uint32_t ah = sb + st * G_STAGE;
        #pragma unroll
        for (int i = 0; i < 4; i++) {
            int idx = tid + i * 256;
            int row = idx >> 3, ch = idx & 7;
            uint32_t o = (uint32_t)(row * 128) + (uint32_t)((ch * 16) ^ ((row & 7) * 16));
            CP16(ah + o,         (const char*)(Ag + (size_t)row * DD + k0) + ch * 16);
            CP16(ah + 16384 + o, (const char*)(Bg + (size_t)row * DD + k0) + ch * 16);
        }
        CP_COMMIT();
    };

    const int wid = tid >> 5, lane = tid & 31;
    const int wm = wid >> 2, wn = wid & 3;      // warp grid 2x4
    const int m0 = wm * 64, n0 = wn * 32;
    const int gid = lane >> 2, tig = lane & 3;

    const int a_r = lane & 15;
    const uint32_t a_k = ((lane >> 4) & 1) * 16;
    const uint32_t a_x = (uint32_t)((a_r & 7) * 16);
    const int b_r = (lane & 7) + ((lane >> 4) & 1) * 8;
    const uint32_t b_k = ((lane >> 3) & 1) * 16;
    const uint32_t b_x = (uint32_t)((lane & 7) * 16);

    float acc[4][4][4];
    #pragma unroll
    for (int mt = 0; mt < 4; mt++)
        #pragma unroll
        for (int nt = 0; nt < 4; nt++)
            #pragma unroll
            for (int q = 0; q < 4; q++) acc[mt][nt][q] = 0.0f;

    cp_chunk(0, 0);
    cp_chunk(1, 1);

    for (int c = 0; c < 16; c++) {
        if (c + 2 < 16) { cp_chunk(c + 2, (c + 2) % 3); CP_WAIT(2); }
        else if (c + 1 < 16) { CP_WAIT(1); }
        else { CP_WAIT(0); }
        __syncthreads();

        const uint32_t base = sb + (c % 3) * G_STAGE;
        #pragma unroll
        for (int kk = 0; kk < 4; kk++) {
            const uint32_t ka = ((uint32_t)(kk * 32) + a_k) ^ a_x;
            const uint32_t kb = ((uint32_t)(kk * 32) + b_k) ^ b_x;
            uint32_t a[4][4], bh[2][4];
            #pragma unroll
            for (int mt = 0; mt < 4; mt++) {
                uint32_t ra = base + (uint32_t)((m0 + mt * 16 + a_r) * 128);
                LDSM4(a[mt][0], a[mt][1], a[mt][2], a[mt][3], ra + ka);
            }
            #pragma unroll
            for (int p = 0; p < 2; p++) {
                uint32_t rb = base + 16384 + (uint32_t)((n0 + p * 16 + b_r) * 128);
                LDSM4(bh[p][0], bh[p][1], bh[p][2], bh[p][3], rb + kb);
            }
            #pragma unroll
            for (int mt = 0; mt < 4; mt++)
                #pragma unroll
                for (int nt = 0; nt < 4; nt++) {
                    const int p = nt >> 1, hf = (nt & 1) * 2;
                    MMA_F16(acc[mt][nt][0], acc[mt][nt][1], acc[mt][nt][2], acc[mt][nt][3],
                            a[mt][0], a[mt][1], a[mt][2], a[mt][3],
                            bh[p][hf], bh[p][hf + 1]);
                }
        }
        __syncthreads();
    }

    #pragma unroll
    for (int nt = 0; nt < 4; nt++) {
        const int col = nbase + n0 + nt * 8 + tig * 2;
        float2 bv = *(const float2*)&g_biasp[col];
        #pragma unroll
        for (int mt = 0; mt < 4; mt++) {
            const int row = mbase + m0 + mt * 16 + gid;
            __half2 v0 = __floats2half2_rn(acc[mt][nt][0] + bv.x, acc[mt][nt][1] + bv.y);
            __half2 v1 = __floats2half2_rn(acc[mt][nt][2] + bv.x, acc[mt][nt][3] + bv.y);
            *(__half2*)&g_xw[(size_t)row * FOURH + col] = v0;
            *(__half2*)&g_xw[(size_t)(row + 8) * FOURH + col] = v1;
        }
    }
}

// ---------------------------------------------------------------------------
// Persistent LSTM recurrence, single fp16 term: D = Wh . h^T.
// 128 CTAs x 256 threads. CTA jb owns j' [jb*32, jb*32+32). Warp w owns batch
// rows [w*8, w*8+8). Wh resident (64KB); full step's h prefetched (128KB).
// Rendezvous: per-CTA release-flags (128B strided) + block-parallel acquire
// poll (__syncthreads_and). out[] store + next-step xw prefetch moved AFTER
// the flag publish (off the inter-CTA critical path).
// ---------------------------------------------------------------------------
#define PA     0                 // 64KB Wh slice, 16 chunks x 4KB
#define PB     65536             // 16 stages x 8KB (h fp16) = 128KB
#define PXW    196608            // 2 x 4KB xw tile (double buffered)
#define PASW   204800            // 8 warps x 1152B staging
#define P_SMEM (204800 + 9216)   // 214016 B

__global__ __launch_bounds__(256, 1)
void lstm_persistent(float* __restrict__ out) {
    extern __shared__ char smem[];
    const uint32_t sb = smem_u32(smem);
    const int tid = threadIdx.x;
    const int jb = blockIdx.x;                 // 0..127
    const int wid = tid >> 5, lane = tid & 31;
    const int n0 = wid * 8;                    // warp's batch rows
    const int gid = lane >> 2, tig = lane & 3;
    const int rot = jb >> 3;                   // chunk-order rotation

    // A (Wh) ldmatrix addressing
    const int a_r = lane & 15;
    const uint32_t a_k = ((lane >> 4) & 1) * 16;
    const uint32_t a_x = (uint32_t)((a_r & 7) * 16);
    // B ldmatrix addressing (n8 x k32 via x4)
    const int b_row = lane & 7;
    const int b_mat = lane >> 3;

    // ---- load persistent Wh slice (16 k-chunks x 32 rows x 128B) ----
    {
        const __half* Ahg = g_wht + (size_t)jb * 32 * DD;
        #pragma unroll
        for (int i = 0; i < 16; i++) {
            int idx = tid + i * 256;
            int c = idx >> 8;
            int row = (idx >> 3) & 31;
            int ch = idx & 7;
            uint32_t o = (uint32_t)(c * 4096 + row * 128)
                       + (uint32_t)((ch * 16) ^ ((row & 7) * 16));
            CP16(sb + PA + o, (const char*)(Ahg + (size_t)row * DD + c * 64) + ch * 16);
        }
        CP_COMMIT();
        CP_WAIT(0);
        __syncthreads();
    }

    float creg[2] = {0.0f, 0.0f};

    // precomputed per-lane offsets for B loads (2 CP16 per chunk per lane)
    const int bl_row0 = lane >> 3;
    const int bl_ch0  = lane & 7;
    const int bl_row1 = (lane + 32) >> 3;
    const int bl_ch1  = lane & 7;
    const uint32_t bo0 = (uint32_t)((n0 + bl_row0) * 128) + (uint32_t)((bl_ch0 * 16) ^ (bl_row0 * 16));
    const uint32_t bo1 = (uint32_t)((n0 + bl_row1) * 128) + (uint32_t)((bl_ch1 * 16) ^ (bl_row1 * 16));
    const int xw_row = lane >> 2, xw_ch = lane & 3;

    // initial xw prefetch for t=0 into buffer 0 (joins chunk-0 commit group)
    CP16(sb + PXW + (uint32_t)(wid * 512 + xw_row * 64 + xw_ch * 16),
         (const char*)(g_xw + ((size_t)(n0 + xw_row) * TT + 0) * FOURH + jb * 32) + xw_ch * 16);

    for (unsigned t = 0; t < TT; t++) {
        const __half* Bg = g_h[t & 1];

        // ---- fire-and-forget: ALL 16 h chunks (one commit group each) ----
        #pragma unroll
        for (int cc = 0; cc < 16; cc++) {
            const int c = (cc + rot) & 15;
            const int k0 = c * 64;
            const uint32_t bb = sb + PB + (uint32_t)(cc * 8192);
            CP16(bb + bo0, (const char*)(Bg + (size_t)(n0 + bl_row0) * DD + k0) + bl_ch0 * 16);
            CP16(bb + bo1, (const char*)(Bg + (size_t)(n0 + bl_row1) * DD + k0) + bl_ch1 * 16);
            CP_COMMIT();
        }

        // 4 independent accumulator chains: [mt][k16-parity]
        float accE[2][4], accO[2][4];
        #pragma unroll
        for (int mt = 0; mt < 2; mt++)
            #pragma unroll
            for (int q = 0; q < 4; q++) { accE[mt][q] = 0.0f; accO[mt][q] = 0.0f; }

        // ---- pure-issue mainloop; wait counts descend 15..0 ----
        #define STEP_CHUNK(CC)                                                          \
        {                                                                               \
            CP_WAIT(15 - (CC));                                                         \
            __syncwarp();                                                               \
            const int c = ((CC) + rot) & 15;                                            \
            const uint32_t bst = sb + PB + (uint32_t)((CC) * 8192);                     \
            const uint32_t ahc = sb + PA + (uint32_t)(c * 4096);                        \
            _Pragma("unroll")                                                           \
            for (int k2 = 0; k2 < 2; k2++) {                                            \
                uint32_t bh[4];                                                         \
                const uint32_t bo = (uint32_t)((n0 + b_row) * 128)                      \
                                  + (uint32_t)((k2 * 64 + b_mat * 16) ^ (b_row * 16));  \
                LDSM4(bh[0], bh[1], bh[2], bh[3], bst + bo);                            \
                uint32_t a0[2][4], a1[2][4];                                            \
                _Pragma("unroll")                                                       \
                for (int mt = 0; mt < 2; mt++) {                                        \
                    const uint32_t ka0 = ((uint32_t)(k2 * 64) + a_k) ^ a_x;             \
                    const uint32_t ka1 = ((uint32_t)(k2 * 64 + 32) + a_k) ^ a_x;        \
                    const uint32_t ar = (uint32_t)((mt * 16 + a_r) * 128);              \
                    LDSM4(a0[mt][0], a0[mt][1], a0[mt][2], a0[mt][3], ahc + ar + ka0);  \
                    LDSM4(a1[mt][0], a1[mt][1], a1[mt][2], a1[mt][3], ahc + ar + ka1);  \
                }                                                                       \
                _Pragma("unroll")                                                       \
                for (int mt = 0; mt < 2; mt++)                                          \
                    MMA_F16(accE[mt][0], accE[mt][1], accE[mt][2], accE[mt][3],         \
                            a0[mt][0], a0[mt][1], a0[mt][2], a0[mt][3], bh[0], bh[1]);  \
                _Pragma("unroll")                                                       \
                for (int mt = 0; mt < 2; mt++)                                          \
                    MMA_F16(accO[mt][0], accO[mt][1], accO[mt][2], accO[mt][3],         \
                            a1[mt][0], a1[mt][1], a1[mt][2], a1[mt][3], bh[2], bh[3]);  \
            }                                                                           \
        }
        STEP_CHUNK(0)  STEP_CHUNK(1)  STEP_CHUNK(2)  STEP_CHUNK(3)
        STEP_CHUNK(4)  STEP_CHUNK(5)  STEP_CHUNK(6)  STEP_CHUNK(7)
        STEP_CHUNK(8)  STEP_CHUNK(9)  STEP_CHUNK(10) STEP_CHUNK(11)
        STEP_CHUNK(12) STEP_CHUNK(13) STEP_CHUNK(14) STEP_CHUNK(15)
        #undef STEP_CHUNK

        // merge chains, stage acc -> asw[n_local][j'] (stride 36), gates
        float* asw = (float*)(smem + PASW + wid * 1152);
        #pragma unroll
        for (int mt = 0; mt < 2; mt++) {
            asw[(tig * 2 + 0) * 36 + mt * 16 + gid]     = accE[mt][0] + accO[mt][0];
            asw[(tig * 2 + 1) * 36 + mt * 16 + gid]     = accE[mt][1] + accO[mt][1];
            asw[(tig * 2 + 0) * 36 + mt * 16 + gid + 8] = accE[mt][2] + accO[mt][2];
            asw[(tig * 2 + 1) * 36 + mt * 16 + gid + 8] = accE[mt][3] + accO[mt][3];
        }
        __syncwarp();

        // gates: compute h, store g_h FIRST (consumer-visible state)
        float hv[2];
        int   nidx[2], jgidx[2];
        {
            const __half* xws = (const __half*)(smem + PXW + (t & 1) * 4096) + wid * 256;
            __half* nh = g_h[(t + 1) & 1];
            #pragma unroll
            for (int i = 0; i < 2; i++) {
                const int p = lane + i * 32;    // 0..63
                const int nl = p >> 3;          // 0..7
                const int jhl = p & 7;          // 0..7
                const float* ar = asw + nl * 36 + jhl * 4;
                const __half2* xr = (const __half2*)(xws + nl * 32 + jhl * 4);
                float2 x01 = __half22float2(xr[0]);
                float2 x23 = __half22float2(xr[1]);
                float ig = fsigmoid(ar[0] + x01.x);
                float fg = fsigmoid(ar[1] + x01.y);
                float og = fsigmoid(ar[2] + x23.x);
                float gg = ftanh(ar[3] + x23.y);
                float cn = fg * creg[i] + ig * gg;
                creg[i] = cn;
                float h = og * ftanh(cn);
                const int n = n0 + nl;
                const int jg = jb * 8 + jhl;
                nh[n * HH + jg] = __float2half_rn(h);
                hv[i] = h; nidx[i] = n; jgidx[i] = jg;
            }
        }

        // publish: all g_h stores done -> release flag (per-CTA, no atomics)
        __syncthreads();
        if (tid == 0) st_rel(&g_flags[jb * 32], t + 1u);

        // off-critical-path work: out[] DRAM store + next-step xw prefetch
        #pragma unroll
        for (int i = 0; i < 2; i++)
            out[((size_t)nidx[i] * TT + t) * HH + jgidx[i]] = hv[i];
        if (t + 1 < TT) {
            CP16(sb + PXW + (uint32_t)(((t + 1) & 1) * 4096 + wid * 512 + xw_row * 64 + xw_ch * 16),
                 (const char*)(g_xw + ((size_t)(n0 + xw_row) * TT + (t + 1)) * FOURH + jb * 32) + xw_ch * 16);
        }

        // block-parallel acquire poll: thread i watches CTA i's flag
        {
            int ok;
            do {
                unsigned v = (tid < P_CTAS) ? ld_acq(&g_flags[tid * 32]) : 0xFFFFFFFFu;
                ok = __syncthreads_and((tid < P_CTAS) ? (int)(v >= t + 1u) : 1);
            } while (!ok);
        }
    }
}

// ---------------------------------------------------------------------------
extern "C" void kernel_launch(void* const* d_in, const int* in_sizes, int n_in,
                              void* d_out, int out_size)
{
    const float* x  = (const float*)d_in[0];   // (64, 512, 1024)
    const float* h0 = (const float*)d_in[1];   // (64, 1024)
    const float* Wx = (const float*)d_in[2];   // (1024, 4096)
    const float* Wh = (const float*)d_in[3];   // (1024, 4096)
    const float* b  = (const float*)d_in[4];   // (4096,)
    float* out = (float*)d_out;                // (64, 512, 1024)

    cudaFuncSetAttribute(xw_gemm_mma,     cudaFuncAttributeMaxDynamicSharedMemorySize, G_SMEM);
    cudaFuncSetAttribute(lstm_persistent, cudaFuncAttributeMaxDynamicSharedMemorySize, P_SMEM);

    __half *wxt, *wht;
    cudaGetSymbolAddress((void**)&wxt, g_wxt);
    cudaGetSymbolAddress((void**)&wht, g_wht);

    prep_small_kernel<<<64, 1024>>>(h0, b);
    split_x_kernel<<<(NB * TT * DD / 4) / 256, 256>>>(x);
    transpose_perm_kernel<<<dim3(DD / 32, FOURH / 32), dim3(32, 8)>>>(Wx, wxt);
    transpose_perm_kernel<<<dim3(DD / 32, FOURH / 32), dim3(32, 8)>>>(Wh, wht);

    xw_gemm_mma<<<dim3(32, 256), 256, G_SMEM>>>();

    lstm_persistent<<<P_CTAS, 256, P_SMEM>>>(out);
}